// round 14
// baseline (speedup 1.0000x reference)
#include <cuda_runtime.h>
#include <cuda_bf16.h>

#define KCOLS 45
#define NL 5
#define NMAX 8192
#define FDIM 3
#define BDIM 3

#define NBLK   8                     // n's per mega-block
#define NTUP   (NBLK * FDIM)         // 24 tuples per block
#define TPB    320                   // 10 warps
#define NWARP  10

#define NGAUSS 16
#define GSTRIDE 8

// 16-point Gauss-Legendre on [-1,1]: 8 symmetric (x, w) pairs.
__device__ __constant__ float c_gx[8] = {
    0.0950125098376374f, 0.2816035507792589f, 0.4580167776572274f,
    0.6178762444026438f, 0.7554044083550030f, 0.8656312023878318f,
    0.9445750230732326f, 0.9894009349916499f
};
__device__ __constant__ float c_gw[8] = {
    0.1894506104550685f, 0.1826034150449236f, 0.1691565193950025f,
    0.1495959888165767f, 0.1246289712555339f, 0.0951585116824928f,
    0.0622535239386479f, 0.0271524594117541f
};
// pmm = c_pmm[m] * s^m  (= (-1)^m (2m-1)!! s^m)
__device__ __constant__ float c_pmm[9] = {
    1.f, -1.f, 3.f, -15.f, 105.f, -945.f, 10395.f, -135135.f, 2027025.f
};
// 1/(l-m) for the associated-Legendre recurrence
__device__ __constant__ float c_rcp[9] = {
    0.f, 1.f, 0.5f, 1.f/3.f, 0.25f, 0.2f, 1.f/6.f, 1.f/7.f, 0.125f
};

__device__ __forceinline__ float ex2(float x) {
    float r;
    asm("ex2.approx.f32 %0, %1;" : "=f"(r) : "f"(x));
    return r;
}

// ---------------------------------------------------------------------------
// Single mega kernel. Block of 8 n's (24 tuples), 320 threads.
// SH parallelized over (tuple=lane, m=warp). rho on threads 248..319 with
// 16-pt Gauss + Euler-Maclaurin h^2 correction (matches reference trapezoid).
// smem (floats): coef 48 | gauss 128 | odf_s 1080 | rho_s 360 | w_s 24
// ---------------------------------------------------------------------------
__global__ void __launch_bounds__(TPB, 5)
mega_kernel(const float* __restrict__ dirs,
            const float* __restrict__ weights,
            const float4* __restrict__ shapes,
            const int* __restrict__ num_t_ptr,
            float* __restrict__ S,
            float* __restrict__ odf,
            float* __restrict__ ev,
            int N) {
    extern __shared__ float sm[];
    float* coef_s  = sm;                               // 48 (45 used)
    float* gauss_s = coef_s + 48;                      // 128 ([6] of node0 = C12)
    float* odf_s   = gauss_s + NGAUSS * GSTRIDE;       // 1080
    float* rho_s   = odf_s + NTUP * KCOLS;             // 360, layout (nl,b,f,l)
    float* w_s     = rho_s + NTUP * NL * BDIM;         // 24

    int tid  = threadIdx.x;
    int wid  = tid >> 5;
    int lane = tid & 31;
    int n0   = blockIdx.x * NBLK;
    int nloc = N - n0; if (nloc > NBLK) nloc = NBLK;
    int ntup = nloc * FDIM;

    // ---- Phase -1a: SH normalization coefs (fp32, 45 threads) ----
    if (tid < KCOLS) {
        int col = tid;
        int l, base;
        if      (col >= 28) { l = 8; base = 28; }
        else if (col >= 15) { l = 6; base = 15; }
        else if (col >= 6)  { l = 4; base = 6;  }
        else if (col >= 1)  { l = 2; base = 1;  }
        else                { l = 0; base = 0;  }
        int m  = col - base - l;
        int ma = m < 0 ? -m : m;
        float r = 1.0f;
        for (int q = l - ma + 1; q <= l + ma; q++) r *= (float)q;
        float nrm = sqrtf((2.0f * l + 1.0f) * 0.07957747154594767f / r);
        coef_s[col] = (ma == 0) ? nrm : nrm * 1.4142135623730951f;
    }

    // ---- Phase -1b: Gauss node table (16 threads: 64..79) ----
    if (tid >= 64 && tid < 64 + NGAUSS) {
        int j = tid - 64;
        int p = j >> 1;
        float sgn = (j & 1) ? 1.0f : -1.0f;
        float t = fmaf(0.5f * sgn, c_gx[p], 0.5f);       // node on [0,1]
        int num_t = *num_t_ptr;
        float scale = (num_t > 0) ? (float)(num_t - 1) / (float)num_t : 1.0f;
        float gw = 0.5f * c_gw[p] * scale;
        const float recip[8] = {1.f, 0.5f, 1.f/3.f, 0.25f, 0.2f, 1.f/6.f, 1.f/7.f, 0.125f};
        float P[9];
        P[0] = 1.0f; P[1] = t;
        #pragma unroll
        for (int n = 1; n < 8; n++)
            P[n + 1] = ((2.0f * n + 1.0f) * t * P[n] - (float)n * P[n - 1]) * recip[n];
        float* g = &gauss_s[j * GSTRIDE];
        g[0] = t * t;
        #pragma unroll
        for (int l = 0; l < 5; l++) g[1 + l] = gw * P[2 * l];
        // node 0 slot 6 carries the Euler-Maclaurin constant:
        // reference = scale*(integral + h^2/12*(f'(1)-f'(0))), h = 1/(num_t-1)
        // C12 = scale*h^2/12 = 1/(12*num_t*(num_t-1))
        g[6] = (j == 0 && num_t > 1)
             ? 1.0f / (12.0f * (float)num_t * (float)(num_t - 1)) : 0.f;
        g[7] = 0.f;
    }

    // ---- Phase -1c: weights (threads 128..) ----
    if (tid >= 128 && tid < 128 + ntup)
        w_s[tid - 128] = __ldg(&weights[n0 * FDIM + tid - 128]);
    __syncthreads();   // coef_s, gauss_s, w_s

    // ---- Phase 0a: SH basis — warp = m (0..8), lane = tuple ----
    if (wid < 9 && lane < ntup) {
        int m = wid;
        int t = lane;
        int tuple = n0 * FDIM + t;

        float x = dirs[tuple * 3 + 0];
        float y = dirs[tuple * 3 + 1];
        float z = dirs[tuple * 3 + 2];
        float inv = rsqrtf(x * x + y * y + z * z);
        x *= inv; y *= inv; z *= inv;

        float s2 = fminf(fmaxf(1.0f - z * z, 0.0f), 1.0f);
        float s = sqrtf(s2);

        float rxy = sqrtf(x * x + y * y);
        bool  havexy = rxy > 0.0f;
        float invr = havexy ? (1.0f / rxy) : 0.0f;
        float cphi = havexy ? x * invr : 1.0f;
        float sphi = y * invr;

        // pmm, cos(m phi), sin(m phi) — uniform trip count per warp
        float spow = 1.0f;
        float cm = 1.0f, sm_ = 0.0f;
        for (int i = 0; i < m; i++) {
            spow *= s;
            float cn = cm * cphi - sm_ * sphi;
            float sn = sm_ * cphi + cm * sphi;
            cm = cn; sm_ = sn;
        }
        float p_prev = c_pmm[m] * spow;    // P(m,m)

        float* val = &odf_s[t * KCOLS];

#define SH_EMIT_RT(L, P)                                                     \
        {                                                                    \
            int bi = ((L) >> 1) * ((L) - 1);                                 \
            float cf = coef_s[bi + (L) + m];                                 \
            float v = cf * (P);                                              \
            if (m == 0) val[bi + (L)] = v;                                   \
            else { val[bi + (L) + m] = v * cm; val[bi + (L) - m] = v * sm_; }\
        }

        if ((m & 1) == 0) SH_EMIT_RT(m, p_prev);
        if (m < 8) {
            float p_cur = (2.0f * m + 1.0f) * z * p_prev;   // P(m+1,m)
            if (((m + 1) & 1) == 0) SH_EMIT_RT(m + 1, p_cur);
            for (int l = m + 2; l <= 8; l++) {
                float p_next = ((2.0f * l - 1.0f) * z * p_cur -
                                (float)(l + m - 1) * p_prev) * c_rcp[l - m];
                p_prev = p_cur; p_cur = p_next;
                if ((l & 1) == 0) SH_EMIT_RT(l, p_cur);
            }
        }
#undef SH_EMIT_RT
    }

    // ---- Phase 0b: rho, threads 248..319 (one per (tuple, b)) ----
    if (tid >= 248 && tid < 248 + ntup * BDIM) {
        int idx = tid - 248;
        int tu  = idx / BDIM;
        int b   = idx - tu * BDIM;
        int nl  = tu / FDIM;
        int f   = tu - nl * FDIM;
        float bv = (float)(b + 1);

        float4 sp = __ldg(&shapes[n0 * FDIM + tu]);   // {D_a, D_epar, D_eperp, z}
        float z = sp.w, omz = 1.0f - z;
        const float LOG2E = 1.4426950408889634f;
        const float LN2   = 0.6931471805599453f;
        float a1 = -bv * sp.x * LOG2E;                 // exp2 coef for alpha1=b*Da
        float a2 = -bv * (sp.y - sp.z) * LOG2E;        // exp2 coef for alpha2=b*dd
        float c2 = omz * ex2(-bv * sp.z * LOG2E);      // (1-z) e^{-b*Deperp}

        float acc[5] = {0.f, 0.f, 0.f, 0.f, 0.f};
        #pragma unroll
        for (int j = 0; j < NGAUSS; j++) {
            const float4* g4 = (const float4*)&gauss_s[j * GSTRIDE];
            float4 ga = g4[0];            // {t2, wP0, wP2, wP4}
            float4 gb = g4[1];            // {wP6, wP8, C12?, 0}
            float t2 = ga.x;
            float e1 = ex2(a1 * t2);
            float e2 = ex2(a2 * t2);
            float kj = fmaf(z, e1, c2 * e2);
            acc[0] = fmaf(kj, ga.y, acc[0]);
            acc[1] = fmaf(kj, ga.z, acc[1]);
            acc[2] = fmaf(kj, ga.w, acc[2]);
            acc[3] = fmaf(kj, gb.x, acc[3]);
            acc[4] = fmaf(kj, gb.y, acc[4]);
        }

        // Euler-Maclaurin h^2 correction: + C12 * sum of
        //   cc * (L_l - 2*alpha) per exponential, L_l = l(l+1)/2.
        {
            float C12 = gauss_s[6];
            float alpha1 = -a1 * LN2;
            float alpha2 = -a2 * LN2;
            float cc1 = C12 * z  * ex2(a1);      // C12 * z * e^{-alpha1}
            float cc2 = C12 * c2 * ex2(a2);      // C12 * (1-z)e^{-b Deperp} e^{-alpha2}
            float ta1 = -2.0f * alpha1, ta2 = -2.0f * alpha2;
            const float Lt[5] = {0.f, 3.f, 10.f, 21.f, 36.f};
            #pragma unroll
            for (int l = 0; l < 5; l++)
                acc[l] += fmaf(cc1, Lt[l] + ta1, cc2 * (Lt[l] + ta2));
        }

        float* o = &rho_s[((nl * BDIM + b) * FDIM + f) * NL];
        #pragma unroll
        for (int l = 0; l < 5; l++) o[l] = acc[l];
    }
    __syncthreads();   // odf_s, rho_s ready

    // Lane-constant k / li for the 45-wide row emits.
    int k1 = lane;                 // always < 45
    int k2 = lane + 32;            // valid when lane < 13
    int li1 = (k1 >= 1) + (k1 >= 6) + (k1 >= 15) + (k1 >= 28);
    int li2 = (k2 >= 15) ? ((k2 >= 28) ? 4 : 3) : 2;
    bool has2 = (lane < KCOLS - 32);

    // ---- emit ev: warp-per-row; rho_s rows == ev rows ----
    {
        int nrows = nloc * BDIM * FDIM;            // 72 full
        float* gbase = ev + (size_t)n0 * BDIM * FDIM * KCOLS;
        for (int row = wid; row < nrows; row += NWARP) {
            const float* rr = &rho_s[row * NL];
            float* g = gbase + row * KCOLS;
            g[k1] = rr[li1];
            if (has2) g[k2] = rr[li2];
        }
    }

    // ---- emit S: warp-per-row, computed directly to global ----
    {
        int nrows = nloc * BDIM;                   // 24 full
        float* gbase = S + (size_t)n0 * BDIM * KCOLS;
        for (int row = wid; row < nrows; row += NWARP) {
            int nl = row / BDIM;
            int b  = row - nl * BDIM;
            const float* rb = &rho_s[(nl * BDIM + b) * FDIM * NL];
            float w0 = w_s[nl * FDIM + 0];
            float w1 = w_s[nl * FDIM + 1];
            float w2 = w_s[nl * FDIM + 2];
            const float* o0 = &odf_s[(nl * FDIM + 0) * KCOLS];
            const float* o1 = &odf_s[(nl * FDIM + 1) * KCOLS];
            const float* o2 = &odf_s[(nl * FDIM + 2) * KCOLS];
            float* g = gbase + row * KCOLS;
            {
                float acc = w0 * rb[0 * NL + li1] * o0[k1];
                acc = fmaf(w1 * rb[1 * NL + li1], o1[k1], acc);
                acc = fmaf(w2 * rb[2 * NL + li1], o2[k1], acc);
                g[k1] = acc;
            }
            if (has2) {
                float acc = w0 * rb[0 * NL + li2] * o0[k2];
                acc = fmaf(w1 * rb[1 * NL + li2], o1[k2], acc);
                acc = fmaf(w2 * rb[2 * NL + li2], o2[k2], acc);
                g[k2] = acc;
            }
        }
    }

    // ---- emit odf (float4 linear copy) ----
    {
        int total = ntup * KCOLS;                  // 1080 full
        int nv = total >> 2;
        float* gbase = odf + (size_t)n0 * FDIM * KCOLS;
        float4* dst = (float4*)gbase;
        const float4* src = (const float4*)odf_s;
        for (int i = tid; i < nv; i += TPB) dst[i] = src[i];
        for (int i = (nv << 2) + tid; i < total; i += TPB) gbase[i] = odf_s[i];
    }
}

// ---------------------------------------------------------------------------
extern "C" void kernel_launch(void* const* d_in, const int* in_sizes, int n_in,
                              void* d_out, int out_size) {
    const float* directs = (const float*)d_in[0];  // (N, F, 3)
    const float* weights = (const float*)d_in[1];  // (N, F)
    const float* shapes  = (const float*)d_in[2];  // (N, F, 4)
    const int*   num_t   = (const int*)d_in[3];    // scalar

    int N = in_sizes[0] / (FDIM * 3);
    if (N > NMAX) N = NMAX;

    float* out = (float*)d_out;
    float* S   = out;                                   // (N, B, 45)
    float* odf = out + (size_t)N * BDIM * KCOLS;        // (N, F, 45)
    float* ev  = odf + (size_t)N * FDIM * KCOLS;        // (N, B, F, 45)

    const int smem_bytes = (48 + NGAUSS * GSTRIDE + NTUP * KCOLS +
                            NTUP * NL * BDIM + NTUP) * 4;
    int nblocks = (N + NBLK - 1) / NBLK;

    mega_kernel<<<nblocks, TPB, smem_bytes>>>(directs, weights,
                                              (const float4*)shapes, num_t,
                                              S, odf, ev, N);
}

// round 15
// speedup vs baseline: 1.2661x; 1.2661x over previous
#include <cuda_runtime.h>
#include <cuda_bf16.h>

#define KCOLS 45
#define NL 5
#define NMAX 8192
#define FDIM 3
#define BDIM 3

#define NBLK   8                     // n's per mega-block
#define NTUP   (NBLK * FDIM)         // 24 tuples per block
#define TPB    256                   // 8 warps

#define NGAUSS 16
#define GSTRIDE 8

// 16-point Gauss-Legendre on [-1,1]: 8 symmetric (x, w) pairs.
__device__ __constant__ float c_gx[8] = {
    0.0950125098376374f, 0.2816035507792589f, 0.4580167776572274f,
    0.6178762444026438f, 0.7554044083550030f, 0.8656312023878318f,
    0.9445750230732326f, 0.9894009349916499f
};
__device__ __constant__ float c_gw[8] = {
    0.1894506104550685f, 0.1826034150449236f, 0.1691565193950025f,
    0.1495959888165767f, 0.1246289712555339f, 0.0951585116824928f,
    0.0622535239386479f, 0.0271524594117541f
};

__device__ __forceinline__ float ex2(float x) {
    float r;
    asm("ex2.approx.f32 %0, %1;" : "=f"(r) : "f"(x));
    return r;
}

// ---------------------------------------------------------------------------
// Single mega kernel (R13 structure + Euler-Maclaurin correction + input
// prefetch). Block of 8 n's (24 tuples), 256 threads.
// smem (floats): coef 48 | gauss 128 | odf_s 1080 | rho_s 360 | w_s 24
// ---------------------------------------------------------------------------
__global__ void __launch_bounds__(TPB, 6)
mega_kernel(const float* __restrict__ dirs,
            const float* __restrict__ weights,
            const float4* __restrict__ shapes,
            const int* __restrict__ num_t_ptr,
            float* __restrict__ S,
            float* __restrict__ odf,
            float* __restrict__ ev,
            int N) {
    extern __shared__ float sm[];
    float* coef_s  = sm;                               // 48 (45 used)
    float* gauss_s = coef_s + 48;                      // 128 ([6] of node0 = C12)
    float* odf_s   = gauss_s + NGAUSS * GSTRIDE;       // 1080
    float* rho_s   = odf_s + NTUP * KCOLS;             // 360, layout (nl,b,f,l)
    float* w_s     = rho_s + NTUP * NL * BDIM;         // 24

    int tid  = threadIdx.x;
    int wid  = tid >> 5;
    int lane = tid & 31;
    int n0   = blockIdx.x * NBLK;
    int nloc = N - n0; if (nloc > NBLK) nloc = NBLK;
    int ntup = nloc * FDIM;

    // ---- Prefetch inputs at kernel entry (latency hidden under phase -1) ----
    float dx = 0.f, dy = 0.f, dz = 0.f;
    if (tid < ntup) {
        int tuple = n0 * FDIM + tid;
        dx = dirs[tuple * 3 + 0];
        dy = dirs[tuple * 3 + 1];
        dz = dirs[tuple * 3 + 2];
    }
    float4 sp = make_float4(0.f, 0.f, 0.f, 0.f);
    if (tid >= 32 && tid < 32 + ntup * BDIM) {
        int tu = (tid - 32) / BDIM;
        sp = __ldg(&shapes[n0 * FDIM + tu]);
    }

    // ---- Phase -1a: SH normalization coefs (fp32, 45 threads) ----
    if (tid < KCOLS) {
        int col = tid;
        int l, base;
        if      (col >= 28) { l = 8; base = 28; }
        else if (col >= 15) { l = 6; base = 15; }
        else if (col >= 6)  { l = 4; base = 6;  }
        else if (col >= 1)  { l = 2; base = 1;  }
        else                { l = 0; base = 0;  }
        int m  = col - base - l;
        int ma = m < 0 ? -m : m;
        float r = 1.0f;
        for (int q = l - ma + 1; q <= l + ma; q++) r *= (float)q;
        float nrm = sqrtf((2.0f * l + 1.0f) * 0.07957747154594767f / r);
        coef_s[col] = (ma == 0) ? nrm : nrm * 1.4142135623730951f;
    }

    // ---- Phase -1b: Gauss node table (16 threads: 64..79) ----
    if (tid >= 64 && tid < 64 + NGAUSS) {
        int j = tid - 64;
        int p = j >> 1;
        float sgn = (j & 1) ? 1.0f : -1.0f;
        float t = fmaf(0.5f * sgn, c_gx[p], 0.5f);       // node on [0,1]
        int num_t = *num_t_ptr;
        float scale = (num_t > 0) ? (float)(num_t - 1) / (float)num_t : 1.0f;
        float gw = 0.5f * c_gw[p] * scale;
        const float recip[8] = {1.f, 0.5f, 1.f/3.f, 0.25f, 0.2f, 1.f/6.f, 1.f/7.f, 0.125f};
        float P[9];
        P[0] = 1.0f; P[1] = t;
        #pragma unroll
        for (int n = 1; n < 8; n++)
            P[n + 1] = ((2.0f * n + 1.0f) * t * P[n] - (float)n * P[n - 1]) * recip[n];
        float* g = &gauss_s[j * GSTRIDE];
        g[0] = t * t;
        #pragma unroll
        for (int l = 0; l < 5; l++) g[1 + l] = gw * P[2 * l];
        // node 0 slot 6: Euler-Maclaurin constant C12 = 1/(12*num_t*(num_t-1)),
        // reproducing the reference trapezoid's h^2 bias.
        g[6] = (j == 0 && num_t > 1)
             ? 1.0f / (12.0f * (float)num_t * (float)(num_t - 1)) : 0.f;
        g[7] = 0.f;
    }

    // ---- Phase -1c: weights (threads 128..) ----
    if (tid >= 128 && tid < 128 + ntup)
        w_s[tid - 128] = __ldg(&weights[n0 * FDIM + tid - 128]);
    __syncthreads();   // coef_s, gauss_s, w_s

    // ---- Phase 0a: SH basis (tid < ntup), inputs already in registers ----
    if (tid < ntup) {
        float x = dx, y = dy, z = dz;
        float inv = rsqrtf(x * x + y * y + z * z);
        x *= inv; y *= inv; z *= inv;

        float s2 = fminf(fmaxf(1.0f - z * z, 0.0f), 1.0f);
        float s = sqrtf(s2);

        float rxy = sqrtf(x * x + y * y);
        bool  havexy = rxy > 0.0f;
        float invr = havexy ? (1.0f / rxy) : 0.0f;
        float cphi = havexy ? x * invr : 1.0f;
        float sphi = y * invr;

        float* val = &odf_s[tid * KCOLS];
        const int base[5] = {0, 1, 6, 15, 28};

#define SH_EMIT(L, M, Pv)                                                    \
        {                                                                    \
            int bi = base[(L) >> 1];                                        \
            float cf = coef_s[bi + (L) + (M)];                              \
            if ((M) == 0) {                                                 \
                val[bi + (L)] = cf * (Pv);                                  \
            } else {                                                        \
                val[bi + (L) + (M)] = cf * (Pv) * cm;                       \
                val[bi + (L) - (M)] = cf * (Pv) * sm_;                      \
            }                                                                \
        }

        float pmm = 1.0f;
        float cm = 1.0f, sm_ = 0.0f;
        #pragma unroll
        for (int m = 0; m <= 8; m++) {
            float p_prev = pmm;
            if ((m & 1) == 0) SH_EMIT(m, m, p_prev);
            if (m < 8) {
                float p_cur = (2.0f * m + 1.0f) * z * p_prev;
                if (((m + 1) & 1) == 0) SH_EMIT(m + 1, m, p_cur);
                #pragma unroll
                for (int l = m + 2; l <= 8; l++) {
                    float p_next = ((2.0f * l - 1.0f) * z * p_cur -
                                    (float)(l + m - 1) * p_prev)
                                   * (1.0f / (float)(l - m));
                    p_prev = p_cur; p_cur = p_next;
                    if ((l & 1) == 0) SH_EMIT(l, m, p_cur);
                }
            }
            pmm = -(2.0f * m + 1.0f) * s * pmm;
            float cn = cm * cphi - sm_ * sphi;
            float sn = sm_ * cphi + cm * sphi;
            cm = cn; sm_ = sn;
        }
#undef SH_EMIT
    }

    // ---- Phase 0b: rho, one thread per (tuple, b), warps 1-3 ----
    if (tid >= 32 && tid < 32 + ntup * BDIM) {
        int idx = tid - 32;
        int tu  = idx / BDIM;
        int b   = idx - tu * BDIM;
        int nl  = tu / FDIM;
        int f   = tu - nl * FDIM;
        float bv = (float)(b + 1);

        float z = sp.w, omz = 1.0f - z;
        const float LOG2E = 1.4426950408889634f;
        const float LN2   = 0.6931471805599453f;
        float a1 = -bv * sp.x * LOG2E;                 // exp2 coef for alpha1=b*Da
        float a2 = -bv * (sp.y - sp.z) * LOG2E;        // exp2 coef for alpha2=b*dd
        float c2 = omz * ex2(-bv * sp.z * LOG2E);      // (1-z) e^{-b*Deperp}

        float acc[5] = {0.f, 0.f, 0.f, 0.f, 0.f};
        #pragma unroll
        for (int j = 0; j < NGAUSS; j++) {
            const float4* g4 = (const float4*)&gauss_s[j * GSTRIDE];
            float4 ga = g4[0];            // {t2, wP0, wP2, wP4}
            float4 gb = g4[1];            // {wP6, wP8, C12?, 0}
            float t2 = ga.x;
            float e1 = ex2(a1 * t2);
            float e2 = ex2(a2 * t2);
            float kj = fmaf(z, e1, c2 * e2);
            acc[0] = fmaf(kj, ga.y, acc[0]);
            acc[1] = fmaf(kj, ga.z, acc[1]);
            acc[2] = fmaf(kj, ga.w, acc[2]);
            acc[3] = fmaf(kj, gb.x, acc[3]);
            acc[4] = fmaf(kj, gb.y, acc[4]);
        }

        // Euler-Maclaurin h^2 correction (matches reference trapezoid bias):
        // + C12 * cc * (l(l+1)/2 - 2*alpha) per exponential.
        {
            float C12 = gauss_s[6];
            float alpha1 = -a1 * LN2;
            float alpha2 = -a2 * LN2;
            float cc1 = C12 * z  * ex2(a1);      // C12 * z * e^{-alpha1}
            float cc2 = C12 * c2 * ex2(a2);      // C12 * c2 * e^{-alpha2}
            float ta1 = -2.0f * alpha1, ta2 = -2.0f * alpha2;
            const float Lt[5] = {0.f, 3.f, 10.f, 21.f, 36.f};
            #pragma unroll
            for (int l = 0; l < 5; l++)
                acc[l] += fmaf(cc1, Lt[l] + ta1, cc2 * (Lt[l] + ta2));
        }

        float* o = &rho_s[((nl * BDIM + b) * FDIM + f) * NL];
        #pragma unroll
        for (int l = 0; l < 5; l++) o[l] = acc[l];
    }
    __syncthreads();   // odf_s, rho_s ready

    // Lane-constant k / li for the 45-wide row emits.
    int k1 = lane;                 // always < 45
    int k2 = lane + 32;            // valid when lane < 13
    int li1 = (k1 >= 1) + (k1 >= 6) + (k1 >= 15) + (k1 >= 28);
    int li2 = (k2 >= 15) ? ((k2 >= 28) ? 4 : 3) : 2;
    bool has2 = (lane < KCOLS - 32);

    // ---- emit ev: warp-per-row; rho_s rows == ev rows ----
    {
        int nrows = nloc * BDIM * FDIM;            // 72 full
        float* gbase = ev + (size_t)n0 * BDIM * FDIM * KCOLS;
        for (int row = wid; row < nrows; row += 8) {
            const float* rr = &rho_s[row * NL];
            float* g = gbase + row * KCOLS;
            g[k1] = rr[li1];
            if (has2) g[k2] = rr[li2];
        }
    }

    // ---- emit S: warp-per-row, computed directly to global ----
    {
        int nrows = nloc * BDIM;                   // 24 full
        float* gbase = S + (size_t)n0 * BDIM * KCOLS;
        for (int row = wid; row < nrows; row += 8) {
            int nl = row / BDIM;
            int b  = row - nl * BDIM;
            const float* rb = &rho_s[(nl * BDIM + b) * FDIM * NL];
            float w0 = w_s[nl * FDIM + 0];
            float w1 = w_s[nl * FDIM + 1];
            float w2 = w_s[nl * FDIM + 2];
            const float* o0 = &odf_s[(nl * FDIM + 0) * KCOLS];
            const float* o1 = &odf_s[(nl * FDIM + 1) * KCOLS];
            const float* o2 = &odf_s[(nl * FDIM + 2) * KCOLS];
            float* g = gbase + row * KCOLS;
            {
                float acc = w0 * rb[0 * NL + li1] * o0[k1];
                acc = fmaf(w1 * rb[1 * NL + li1], o1[k1], acc);
                acc = fmaf(w2 * rb[2 * NL + li1], o2[k1], acc);
                g[k1] = acc;
            }
            if (has2) {
                float acc = w0 * rb[0 * NL + li2] * o0[k2];
                acc = fmaf(w1 * rb[1 * NL + li2], o1[k2], acc);
                acc = fmaf(w2 * rb[2 * NL + li2], o2[k2], acc);
                g[k2] = acc;
            }
        }
    }

    // ---- emit odf (float4 linear copy) ----
    {
        int total = ntup * KCOLS;                  // 1080 full
        int nv = total >> 2;
        float* gbase = odf + (size_t)n0 * FDIM * KCOLS;
        float4* dst = (float4*)gbase;
        const float4* src = (const float4*)odf_s;
        for (int i = tid; i < nv; i += TPB) dst[i] = src[i];
        for (int i = (nv << 2) + tid; i < total; i += TPB) gbase[i] = odf_s[i];
    }
}

// ---------------------------------------------------------------------------
extern "C" void kernel_launch(void* const* d_in, const int* in_sizes, int n_in,
                              void* d_out, int out_size) {
    const float* directs = (const float*)d_in[0];  // (N, F, 3)
    const float* weights = (const float*)d_in[1];  // (N, F)
    const float* shapes  = (const float*)d_in[2];  // (N, F, 4)
    const int*   num_t   = (const int*)d_in[3];    // scalar

    int N = in_sizes[0] / (FDIM * 3);
    if (N > NMAX) N = NMAX;

    float* out = (float*)d_out;
    float* S   = out;                                   // (N, B, 45)
    float* odf = out + (size_t)N * BDIM * KCOLS;        // (N, F, 45)
    float* ev  = odf + (size_t)N * FDIM * KCOLS;        // (N, B, F, 45)

    const int smem_bytes = (48 + NGAUSS * GSTRIDE + NTUP * KCOLS +
                            NTUP * NL * BDIM + NTUP) * 4;
    int nblocks = (N + NBLK - 1) / NBLK;

    mega_kernel<<<nblocks, TPB, smem_bytes>>>(directs, weights,
                                              (const float4*)shapes, num_t,
                                              S, odf, ev, N);
}

// round 16
// speedup vs baseline: 1.3692x; 1.0814x over previous
#include <cuda_runtime.h>
#include <cuda_bf16.h>

#define KCOLS 45
#define NL 5
#define NMAX 8192
#define FDIM 3
#define BDIM 3

#define NBLK   8                     // n's per mega-block
#define NTUP   (NBLK * FDIM)         // 24 tuples per block
#define TPB    256                   // 8 warps

#define NGAUSS 16
#define GSTRIDE 8

// 16-point Gauss-Legendre on [-1,1]: 8 symmetric (x, w) pairs.
__device__ __constant__ float c_gx[8] = {
    0.0950125098376374f, 0.2816035507792589f, 0.4580167776572274f,
    0.6178762444026438f, 0.7554044083550030f, 0.8656312023878318f,
    0.9445750230732326f, 0.9894009349916499f
};
__device__ __constant__ float c_gw[8] = {
    0.1894506104550685f, 0.1826034150449236f, 0.1691565193950025f,
    0.1495959888165767f, 0.1246289712555339f, 0.0951585116824928f,
    0.0622535239386479f, 0.0271524594117541f
};

__device__ __forceinline__ float ex2(float x) {
    float r;
    asm("ex2.approx.f32 %0, %1;" : "=f"(r) : "f"(x));
    return r;
}

// ---------------------------------------------------------------------------
// Single mega kernel, templated on FULL (all blocks full: nloc == NBLK
// compile-time, every loop bound constant -> fully unrolled emits).
// smem (floats): coef 48 | gauss 128 | odf_s 1080 | rho_s 360 | w_s 24
// ---------------------------------------------------------------------------
template<bool FULL>
__global__ void __launch_bounds__(TPB, 6)
mega_kernel(const float* __restrict__ dirs,
            const float* __restrict__ weights,
            const float4* __restrict__ shapes,
            const int* __restrict__ num_t_ptr,
            float* __restrict__ S,
            float* __restrict__ odf,
            float* __restrict__ ev,
            int N) {
    extern __shared__ float sm[];
    float* coef_s  = sm;                               // 48 (45 used)
    float* gauss_s = coef_s + 48;                      // 128 ([6] of node0 = C12)
    float* odf_s   = gauss_s + NGAUSS * GSTRIDE;       // 1080
    float* rho_s   = odf_s + NTUP * KCOLS;             // 360, layout (nl,b,f,l)
    float* w_s     = rho_s + NTUP * NL * BDIM;         // 24

    int tid  = threadIdx.x;
    int wid  = tid >> 5;
    int lane = tid & 31;
    int n0   = blockIdx.x * NBLK;
    int nloc, ntup;
    if (FULL) { nloc = NBLK; ntup = NTUP; }
    else {
        nloc = N - n0; if (nloc > NBLK) nloc = NBLK;
        ntup = nloc * FDIM;
    }

    // ---- Prefetch inputs at kernel entry (latency hidden under phase -1) ----
    float dx = 0.f, dy = 0.f, dz = 0.f;
    if (tid < ntup) {
        int tuple = n0 * FDIM + tid;
        dx = dirs[tuple * 3 + 0];
        dy = dirs[tuple * 3 + 1];
        dz = dirs[tuple * 3 + 2];
    }
    float4 sp = make_float4(0.f, 0.f, 0.f, 0.f);
    if (tid >= 32 && tid < 32 + ntup * BDIM) {
        int tu = (tid - 32) / BDIM;
        sp = __ldg(&shapes[n0 * FDIM + tu]);
    }

    // ---- Phase -1a: SH normalization coefs (fp32, 45 threads) ----
    if (tid < KCOLS) {
        int col = tid;
        int l, base;
        if      (col >= 28) { l = 8; base = 28; }
        else if (col >= 15) { l = 6; base = 15; }
        else if (col >= 6)  { l = 4; base = 6;  }
        else if (col >= 1)  { l = 2; base = 1;  }
        else                { l = 0; base = 0;  }
        int m  = col - base - l;
        int ma = m < 0 ? -m : m;
        float r = 1.0f;
        for (int q = l - ma + 1; q <= l + ma; q++) r *= (float)q;
        float nrm = sqrtf((2.0f * l + 1.0f) * 0.07957747154594767f / r);
        coef_s[col] = (ma == 0) ? nrm : nrm * 1.4142135623730951f;
    }

    // ---- Phase -1b: Gauss node table (16 threads: 64..79) ----
    if (tid >= 64 && tid < 64 + NGAUSS) {
        int j = tid - 64;
        int p = j >> 1;
        float sgn = (j & 1) ? 1.0f : -1.0f;
        float t = fmaf(0.5f * sgn, c_gx[p], 0.5f);       // node on [0,1]
        int num_t = *num_t_ptr;
        float scale = (num_t > 0) ? (float)(num_t - 1) / (float)num_t : 1.0f;
        float gw = 0.5f * c_gw[p] * scale;
        const float recip[8] = {1.f, 0.5f, 1.f/3.f, 0.25f, 0.2f, 1.f/6.f, 1.f/7.f, 0.125f};
        float P[9];
        P[0] = 1.0f; P[1] = t;
        #pragma unroll
        for (int n = 1; n < 8; n++)
            P[n + 1] = ((2.0f * n + 1.0f) * t * P[n] - (float)n * P[n - 1]) * recip[n];
        float* g = &gauss_s[j * GSTRIDE];
        g[0] = t * t;
        #pragma unroll
        for (int l = 0; l < 5; l++) g[1 + l] = gw * P[2 * l];
        // node 0 slot 6: Euler-Maclaurin constant C12 = 1/(12*num_t*(num_t-1)),
        // reproducing the reference trapezoid's h^2 bias.
        g[6] = (j == 0 && num_t > 1)
             ? 1.0f / (12.0f * (float)num_t * (float)(num_t - 1)) : 0.f;
        g[7] = 0.f;
    }

    // ---- Phase -1c: weights (threads 128..) ----
    if (tid >= 128 && tid < 128 + ntup)
        w_s[tid - 128] = __ldg(&weights[n0 * FDIM + tid - 128]);
    __syncthreads();   // coef_s, gauss_s, w_s

    // ---- Phase 0a: SH basis (tid < ntup), inputs already in registers ----
    if (tid < ntup) {
        float x = dx, y = dy, z = dz;
        float inv = rsqrtf(x * x + y * y + z * z);
        x *= inv; y *= inv; z *= inv;

        float s2 = fminf(fmaxf(1.0f - z * z, 0.0f), 1.0f);
        float s = sqrtf(s2);

        float rxy = sqrtf(x * x + y * y);
        bool  havexy = rxy > 0.0f;
        float invr = havexy ? (1.0f / rxy) : 0.0f;
        float cphi = havexy ? x * invr : 1.0f;
        float sphi = y * invr;

        float* val = &odf_s[tid * KCOLS];
        const int base[5] = {0, 1, 6, 15, 28};

#define SH_EMIT(L, M, Pv)                                                    \
        {                                                                    \
            int bi = base[(L) >> 1];                                        \
            float cf = coef_s[bi + (L) + (M)];                              \
            if ((M) == 0) {                                                 \
                val[bi + (L)] = cf * (Pv);                                  \
            } else {                                                        \
                val[bi + (L) + (M)] = cf * (Pv) * cm;                       \
                val[bi + (L) - (M)] = cf * (Pv) * sm_;                      \
            }                                                                \
        }

        float pmm = 1.0f;
        float cm = 1.0f, sm_ = 0.0f;
        #pragma unroll
        for (int m = 0; m <= 8; m++) {
            float p_prev = pmm;
            if ((m & 1) == 0) SH_EMIT(m, m, p_prev);
            if (m < 8) {
                float p_cur = (2.0f * m + 1.0f) * z * p_prev;
                if (((m + 1) & 1) == 0) SH_EMIT(m + 1, m, p_cur);
                #pragma unroll
                for (int l = m + 2; l <= 8; l++) {
                    float p_next = ((2.0f * l - 1.0f) * z * p_cur -
                                    (float)(l + m - 1) * p_prev)
                                   * (1.0f / (float)(l - m));
                    p_prev = p_cur; p_cur = p_next;
                    if ((l & 1) == 0) SH_EMIT(l, m, p_cur);
                }
            }
            pmm = -(2.0f * m + 1.0f) * s * pmm;
            float cn = cm * cphi - sm_ * sphi;
            float sn = sm_ * cphi + cm * sphi;
            cm = cn; sm_ = sn;
        }
#undef SH_EMIT
    }

    // ---- Phase 0b: rho, one thread per (tuple, b), warps 1-3 ----
    if (tid >= 32 && tid < 32 + ntup * BDIM) {
        int idx = tid - 32;
        int tu  = idx / BDIM;
        int b   = idx - tu * BDIM;
        int nl  = tu / FDIM;
        int f   = tu - nl * FDIM;
        float bv = (float)(b + 1);

        float z = sp.w, omz = 1.0f - z;
        const float LOG2E = 1.4426950408889634f;
        const float LN2   = 0.6931471805599453f;
        float a1 = -bv * sp.x * LOG2E;                 // exp2 coef for alpha1=b*Da
        float a2 = -bv * (sp.y - sp.z) * LOG2E;        // exp2 coef for alpha2=b*dd
        float c2 = omz * ex2(-bv * sp.z * LOG2E);      // (1-z) e^{-b*Deperp}

        float acc[5] = {0.f, 0.f, 0.f, 0.f, 0.f};
        #pragma unroll
        for (int j = 0; j < NGAUSS; j++) {
            const float4* g4 = (const float4*)&gauss_s[j * GSTRIDE];
            float4 ga = g4[0];            // {t2, wP0, wP2, wP4}
            float4 gb = g4[1];            // {wP6, wP8, C12?, 0}
            float t2 = ga.x;
            float e1 = ex2(a1 * t2);
            float e2 = ex2(a2 * t2);
            float kj = fmaf(z, e1, c2 * e2);
            acc[0] = fmaf(kj, ga.y, acc[0]);
            acc[1] = fmaf(kj, ga.z, acc[1]);
            acc[2] = fmaf(kj, ga.w, acc[2]);
            acc[3] = fmaf(kj, gb.x, acc[3]);
            acc[4] = fmaf(kj, gb.y, acc[4]);
        }

        // Euler-Maclaurin h^2 correction (matches reference trapezoid bias).
        {
            float C12 = gauss_s[6];
            float alpha1 = -a1 * LN2;
            float alpha2 = -a2 * LN2;
            float cc1 = C12 * z  * ex2(a1);
            float cc2 = C12 * c2 * ex2(a2);
            float ta1 = -2.0f * alpha1, ta2 = -2.0f * alpha2;
            const float Lt[5] = {0.f, 3.f, 10.f, 21.f, 36.f};
            #pragma unroll
            for (int l = 0; l < 5; l++)
                acc[l] += fmaf(cc1, Lt[l] + ta1, cc2 * (Lt[l] + ta2));
        }

        float* o = &rho_s[((nl * BDIM + b) * FDIM + f) * NL];
        #pragma unroll
        for (int l = 0; l < 5; l++) o[l] = acc[l];
    }
    __syncthreads();   // odf_s, rho_s ready

    // Lane-constant k / li for the 45-wide row emits.
    int k1 = lane;                 // always < 45
    int k2 = lane + 32;            // valid when lane < 13
    int li1 = (k1 >= 1) + (k1 >= 6) + (k1 >= 15) + (k1 >= 28);
    int li2 = (k2 >= 15) ? ((k2 >= 28) ? 4 : 3) : 2;
    bool has2 = (lane < KCOLS - 32);

    // ---- emit ev: warp-per-row; rho_s rows == ev rows ----
    {
        float* gbase = ev + (size_t)n0 * BDIM * FDIM * KCOLS;
        if (FULL) {
            #pragma unroll
            for (int it = 0; it < NBLK * BDIM * FDIM / 8; it++) {   // 9
                int row = wid + it * 8;
                const float* rr = &rho_s[row * NL];
                float* g = gbase + row * KCOLS;
                g[k1] = rr[li1];
                if (has2) g[k2] = rr[li2];
            }
        } else {
            int nrows = nloc * BDIM * FDIM;
            for (int row = wid; row < nrows; row += 8) {
                const float* rr = &rho_s[row * NL];
                float* g = gbase + row * KCOLS;
                g[k1] = rr[li1];
                if (has2) g[k2] = rr[li2];
            }
        }
    }

    // ---- emit S: warp-per-row, computed directly to global ----
    {
        float* gbase = S + (size_t)n0 * BDIM * KCOLS;
        int nrows = FULL ? (NBLK * BDIM) : (nloc * BDIM);
        #pragma unroll
        for (int it = 0; it < NBLK * BDIM / 8; it++) {              // 3
            int row = wid + it * 8;
            if (!FULL && row >= nrows) break;
            int nl = row / BDIM;
            int b  = row - nl * BDIM;
            const float* rb = &rho_s[(nl * BDIM + b) * FDIM * NL];
            float w0 = w_s[nl * FDIM + 0];
            float w1 = w_s[nl * FDIM + 1];
            float w2 = w_s[nl * FDIM + 2];
            const float* o0 = &odf_s[(nl * FDIM + 0) * KCOLS];
            const float* o1 = &odf_s[(nl * FDIM + 1) * KCOLS];
            const float* o2 = &odf_s[(nl * FDIM + 2) * KCOLS];
            float* g = gbase + row * KCOLS;
            {
                float acc = w0 * rb[0 * NL + li1] * o0[k1];
                acc = fmaf(w1 * rb[1 * NL + li1], o1[k1], acc);
                acc = fmaf(w2 * rb[2 * NL + li1], o2[k1], acc);
                g[k1] = acc;
            }
            if (has2) {
                float acc = w0 * rb[0 * NL + li2] * o0[k2];
                acc = fmaf(w1 * rb[1 * NL + li2], o1[k2], acc);
                acc = fmaf(w2 * rb[2 * NL + li2], o2[k2], acc);
                g[k2] = acc;
            }
        }
    }

    // ---- emit odf (float4 linear copy; 270 float4 per full block) ----
    {
        float* gbase = odf + (size_t)n0 * FDIM * KCOLS;
        float4* dst = (float4*)gbase;
        const float4* src = (const float4*)odf_s;
        if (FULL) {
            // NTUP*KCOLS/4 = 270: all threads once, threads <14 twice.
            dst[tid] = src[tid];
            if (tid < NTUP * KCOLS / 4 - TPB) dst[tid + TPB] = src[tid + TPB];
        } else {
            int total = ntup * KCOLS;
            int nv = total >> 2;
            for (int i = tid; i < nv; i += TPB) dst[i] = src[i];
            for (int i = (nv << 2) + tid; i < total; i += TPB) gbase[i] = odf_s[i];
        }
    }
}

// ---------------------------------------------------------------------------
extern "C" void kernel_launch(void* const* d_in, const int* in_sizes, int n_in,
                              void* d_out, int out_size) {
    const float* directs = (const float*)d_in[0];  // (N, F, 3)
    const float* weights = (const float*)d_in[1];  // (N, F)
    const float* shapes  = (const float*)d_in[2];  // (N, F, 4)
    const int*   num_t   = (const int*)d_in[3];    // scalar

    int N = in_sizes[0] / (FDIM * 3);
    if (N > NMAX) N = NMAX;

    float* out = (float*)d_out;
    float* S   = out;                                   // (N, B, 45)
    float* odf = out + (size_t)N * BDIM * KCOLS;        // (N, F, 45)
    float* ev  = odf + (size_t)N * FDIM * KCOLS;        // (N, B, F, 45)

    const int smem_bytes = (48 + NGAUSS * GSTRIDE + NTUP * KCOLS +
                            NTUP * NL * BDIM + NTUP) * 4;
    int nblocks = (N + NBLK - 1) / NBLK;

    if (N % NBLK == 0)
        mega_kernel<true><<<nblocks, TPB, smem_bytes>>>(directs, weights,
                                                        (const float4*)shapes,
                                                        num_t, S, odf, ev, N);
    else
        mega_kernel<false><<<nblocks, TPB, smem_bytes>>>(directs, weights,
                                                         (const float4*)shapes,
                                                         num_t, S, odf, ev, N);
}